// round 12
// baseline (speedup 1.0000x reference)
#include <cuda_runtime.h>
#include <cuda_bf16.h>
#include <math.h>
#include <stdint.h>

#define BATCH 65536
#define F     512
#define HID   256
#define NCLS  10

// ---------------- scratch ----------------
__device__ __align__(16) unsigned short g_x4h[(size_t)BATCH * F];  // 64 MB
__device__ __align__(16) unsigned short g_x4l[(size_t)BATCH * F];  // 64 MB
__device__ float  g_fc0T[F * F];
__device__ float  g_fc1T[F * F];
__device__ __align__(16) unsigned short g_wHiB[HID * F];
__device__ __align__(16) unsigned short g_wLoB[HID * F];
__device__ float  g_fsum[NCLS * F];
__device__ float  g_l1part[32];
__device__ int    g_counts[NCLS];
__device__ int    g_done;
__device__ double g_s2, g_ce, g_acc;

// ---------------- helpers ----------------
__device__ __forceinline__ uint32_t smem_u32(const void* p) {
    uint32_t a;
    asm("{ .reg .u64 t; cvta.to.shared.u64 t, %1; cvt.u32.u64 %0, t; }"
        : "=r"(a) : "l"(p));
    return a;
}
__device__ __forceinline__ void cpasync16(uint32_t dst, const void* src) {
    asm volatile("cp.async.cg.shared.global [%0], [%1], 16;"
                 :: "r"(dst), "l"(src) : "memory");
}
#define CP_COMMIT() asm volatile("cp.async.commit_group;" ::: "memory")
#define CP_WAIT(n)  asm volatile("cp.async.wait_group %0;" :: "n"(n) : "memory")

__device__ __forceinline__ void ldsm_x4(uint32_t* r, uint32_t addr) {
    asm volatile("ldmatrix.sync.aligned.m8n8.x4.shared.b16 {%0,%1,%2,%3}, [%4];"
                 : "=r"(r[0]), "=r"(r[1]), "=r"(r[2]), "=r"(r[3]) : "r"(addr));
}
__device__ __forceinline__ void mma_tf32(float* c, const uint32_t* a, const uint32_t* b) {
    asm volatile("mma.sync.aligned.m16n8k8.row.col.f32.tf32.tf32.f32 "
                 "{%0,%1,%2,%3}, {%4,%5,%6,%7}, {%8,%9}, {%0,%1,%2,%3};"
                 : "+f"(c[0]), "+f"(c[1]), "+f"(c[2]), "+f"(c[3])
                 : "r"(a[0]), "r"(a[1]), "r"(a[2]), "r"(a[3]), "r"(b[0]), "r"(b[1]));
}
__device__ __forceinline__ void mma_bf16(float* c, const uint32_t* a, const uint32_t* b) {
    asm volatile("mma.sync.aligned.m16n8k16.row.col.f32.bf16.bf16.f32 "
                 "{%0,%1,%2,%3}, {%4,%5,%6,%7}, {%8,%9}, {%0,%1,%2,%3};"
                 : "+f"(c[0]), "+f"(c[1]), "+f"(c[2]), "+f"(c[3])
                 : "r"(a[0]), "r"(a[1]), "r"(a[2]), "r"(a[3]), "r"(b[0]), "r"(b[1]));
}

// ================= prep: transposes + l1 partials + hist + init =================
__global__ __launch_bounds__(1024) void prep_kernel(
    const float* __restrict__ fc0, const float* __restrict__ fc1,
    const float* __restrict__ w, const float* __restrict__ w1,
    const int* __restrict__ y)
{
    __shared__ float t0[32][33];
    __shared__ float t1[32][33];
    __shared__ int   h2[16][12];
    __shared__ float red[32];
    const int b = blockIdx.x;
    const int tid = threadIdx.x;

    if (b < 256) {
        int bx = (b & 15) * 32, by = (b >> 4) * 32;
        int txi = tid & 31, tyi = tid >> 5;
        t0[tyi][txi] = fc0[(by + tyi) * F + bx + txi];
        t1[tyi][txi] = fc1[(by + tyi) * F + bx + txi];
        __syncthreads();
        g_fc0T[(bx + tyi) * F + by + txi] = t0[txi][tyi];
        g_fc1T[(bx + tyi) * F + by + txi] = t1[txi][tyi];
    } else if (b < 384) {
        int bb = b - 256;
        int bx = (bb & 7) * 32, by = (bb >> 3) * 32;
        int txi = tid & 31, tyi = tid >> 5;
        t0[tyi][txi] = w[(by + tyi) * HID + bx + txi];
        __syncthreads();
        float v = t0[txi][tyi];
        __nv_bfloat16 hb = __float2bfloat16(v);
        float hf = __bfloat162float(hb);
        __nv_bfloat16 lb = __float2bfloat16(v - hf);
        size_t o = (size_t)(bx + tyi) * F + by + txi;
        g_wHiB[o] = *(unsigned short*)&hb;
        g_wLoB[o] = *(unsigned short*)&lb;
    } else if (b < 416) {
        float s = 0.f;
        int i0 = (b - 384) * 1024 + tid;
        const int stride = 32 * 1024;
        for (int k = i0; k < F * F; k += stride) s += fabsf(fc0[k]) + fabsf(fc1[k]);
        for (int k = i0; k < F * HID; k += stride) s += fabsf(w[k]);
        for (int k = i0; k < HID * NCLS; k += stride) s += fabsf(w1[k]);
#pragma unroll
        for (int o = 16; o; o >>= 1) s += __shfl_xor_sync(0xffffffffu, s, o);
        if ((tid & 31) == 0) red[tid >> 5] = s;
        __syncthreads();
        if (tid == 0) {
            float t = 0.f;
            for (int i = 0; i < 32; i++) t += red[i];
            g_l1part[b - 384] = t;
        }
    } else if (b == 416) {
        if (tid < 192) ((int*)h2)[tid] = 0;
        __syncthreads();
        int sub = tid & 15;
        for (int i = tid; i < BATCH; i += 1024) atomicAdd(&h2[sub][y[i]], 1);
        __syncthreads();
        if (tid < NCLS) {
            int t = 0;
            for (int s = 0; s < 16; s++) t += h2[s][tid];
            g_counts[tid] = t;
        }
    } else {
        for (int i = tid; i < NCLS * F; i += 1024) g_fsum[i] = 0.f;
        if (tid == 0) { g_s2 = 0.0; g_ce = 0.0; g_acc = 0.0; g_done = 0; }
    }
}

// ============ gate: x4 = x + (1+sigmoid(x@fc0))*relu(x@fc1) ============
// CTA 128 rows x 64 logical cols, 256 threads, 2 CTAs/SM.
// Single-sync pipeline: WAIT(1) -> sync -> mma(ch) -> issue(ch+2).
#define G_STAGE_FL 8192
#define G_CSUM_FL  (3 * G_STAGE_FL)
#define G_RED_FL   (G_CSUM_FL + NCLS * 68)
#define GATE_FL    (G_RED_FL + 8)

__global__ __launch_bounds__(256, 2) void gate_kernel(
    const float* __restrict__ x, const int* __restrict__ y)
{
    extern __shared__ float sm[];
    const uint32_t smb = smem_u32(sm);
    float* csum = sm + G_CSUM_FL;
    float* red  = sm + G_RED_FL;

    const int tid = threadIdx.x;
    const int lane = tid & 31, wid = tid >> 5;
    const int g = lane >> 2, tig = lane & 3;
    const int lane7 = lane & 7;
    const int warpM = wid & 3, warpN = wid >> 2;
    const int rowBase = blockIdx.y * 128;
    const int colBase = blockIdx.x * 64;

    const int rowoffA = ((lane >> 3) & 1) * 8 + lane7;
    const int hA = lane >> 4;
    const int rowoffB = ((lane >> 4) & 1) * 8 + lane7;
    const int hB = (lane >> 3) & 1;

    for (int i = tid; i < NCLS * 68; i += 256) csum[i] = 0.f;

    float acc[2][8][4];
#pragma unroll
    for (int mt = 0; mt < 2; mt++)
#pragma unroll
        for (int nt = 0; nt < 8; nt++)
#pragma unroll
            for (int r = 0; r < 4; r++) acc[mt][nt][r] = 0.f;

    auto issue = [&](int ch) {
        const int p = ch % 3;
        const uint32_t sA = smb + p * (G_STAGE_FL * 4);
        const uint32_t sB = sA + 16384;
        const int kb = ch * 32;
#pragma unroll
        for (int l = 0; l < 4; l++) {
            int idx = l * 256 + tid;
            int r = idx >> 3, q = idx & 7;
            cpasync16(sA + (r * 8 + (q ^ (r & 7))) * 16,
                      &x[(size_t)(rowBase + r) * F + kb + q * 4]);
        }
#pragma unroll
        for (int l = 0; l < 4; l++) {
            int idx = l * 256 + tid;
            int nb = idx >> 3, q = idx & 7;
            int m = (nb >> 3) & 1;
            int L = ((nb >> 4) << 3) | (nb & 7);
            const float* src = (m ? g_fc1T : g_fc0T)
                             + (size_t)(colBase + L) * F + kb + q * 4;
            cpasync16(sB + (nb * 8 + (q ^ (nb & 7))) * 16, src);
        }
        CP_COMMIT();
    };

    issue(0);
    issue(1);

    for (int ch = 0; ch < 16; ch++) {
        CP_WAIT(1);
        __syncthreads();

        const uint32_t stBase = smb + (ch % 3) * (G_STAGE_FL * 4);
        const uint32_t aB0 = stBase + (uint32_t)(warpM * 32 + rowoffA) * 128;
        const uint32_t bB  = stBase + 16384;
        uint32_t bAddr[4];
#pragma unroll
        for (int gi = 0; gi < 4; gi++)
            bAddr[gi] = bB + (uint32_t)(warpN * 64 + gi * 16 + rowoffB) * 128;

#pragma unroll
        for (int s = 0; s < 4; s++) {
            const uint32_t offA = (uint32_t)(((2 * s + hA) ^ lane7) << 4);
            const uint32_t offB = (uint32_t)(((2 * s + hB) ^ lane7) << 4);
            uint32_t a[2][4];
            ldsm_x4(a[0], aB0 + offA);
            ldsm_x4(a[1], aB0 + 2048 + offA);
            uint32_t bq[4][4];
#pragma unroll
            for (int gi = 0; gi < 4; gi++) ldsm_x4(bq[gi], bAddr[gi] + offB);
#pragma unroll
            for (int mt = 0; mt < 2; mt++)
#pragma unroll
                for (int gi = 0; gi < 4; gi++) {
                    mma_tf32(acc[mt][2 * gi],     a[mt], &bq[gi][0]);
                    mma_tf32(acc[mt][2 * gi + 1], a[mt], &bq[gi][2]);
                }
        }

        if (ch < 14) issue(ch + 2); else CP_COMMIT();
    }

    // ---- epilogue: x4 -> bf16 hi/lo split, s2, class sums ----
    float s2loc = 0.f;
#pragma unroll
    for (int mt = 0; mt < 2; mt++) {
        int r0 = rowBase + warpM * 32 + mt * 16 + g;
        int r1 = r0 + 8;
        int y0 = y[r0], y1 = y[r1];
#pragma unroll
        for (int j = 0; j < 4; j++) {
            int lcol = warpN * 32 + j * 8 + 2 * tig;
            int gcol = colBase + lcol;
#pragma unroll
            for (int rr = 0; rr < 2; rr++) {
                int row = rr ? r1 : r0;
                int yr = rr ? y1 : y0;
                float A0x = acc[mt][2 * j][rr * 2],     A0y = acc[mt][2 * j][rr * 2 + 1];
                float A1x = acc[mt][2 * j + 1][rr * 2], A1y = acc[mt][2 * j + 1][rr * 2 + 1];
                float2 xv = *(const float2*)&x[(size_t)row * F + gcol];
                float gx = 1.f + __fdividef(1.f, 1.f + __expf(-A0x));
                float gy = 1.f + __fdividef(1.f, 1.f + __expf(-A0y));
                float ox = xv.x + gx * fmaxf(A1x, 0.f);
                float oy = xv.y + gy * fmaxf(A1y, 0.f);
                __nv_bfloat162 hv = __floats2bfloat162_rn(ox, oy);
                *(uint32_t*)&g_x4h[(size_t)row * F + gcol] = *(uint32_t*)&hv;
                float lx = ox - __bfloat162float(hv.x);
                float ly = oy - __bfloat162float(hv.y);
                __nv_bfloat162 lv = __floats2bfloat162_rn(lx, ly);
                *(uint32_t*)&g_x4l[(size_t)row * F + gcol] = *(uint32_t*)&lv;
                s2loc += ox * ox + oy * oy;
                atomicAdd(&csum[yr * 68 + lcol], ox);
                atomicAdd(&csum[yr * 68 + lcol + 1], oy);
            }
        }
    }
    __syncthreads();

    for (int i = tid; i < NCLS * 64; i += 256) {
        int c = i >> 6, col = i & 63;
        float v = csum[c * 68 + col];
        if (v != 0.f) atomicAdd(&g_fsum[c * F + colBase + col], v);
    }
#pragma unroll
    for (int o = 16; o; o >>= 1) s2loc += __shfl_xor_sync(0xffffffffu, s2loc, o);
    if (lane == 0) red[wid] = s2loc;
    __syncthreads();
    if (tid == 0) {
        float t = 0.f;
        for (int i = 0; i < 8; i++) t += red[i];
        atomicAdd(&g_s2, (double)t);
    }
}

// ============ head: relu(x4@w)@w1, 3-term bf16, BM=64, 2 CTAs/SM ============
// Single-sync pipeline; last CTA (release/acquire done-counter, NO per-CTA
// full fence) performs the final loss/acc assembly.
#define H_STAGE_B  40960
#define H_U_FL     20480
#define H_W1_FL    (H_U_FL)
#define H_PART_FL  (H_U_FL + 2600)
#define H_LOG_FL   (H_PART_FL + 5120)
#define HEAD_FL    (H_LOG_FL + 640)

__global__ __launch_bounds__(256, 2) void head_kernel(
    const float* __restrict__ w1, const int* __restrict__ y,
    float* __restrict__ out)
{
    extern __shared__ float sm[];
    const uint32_t smb = smem_u32(sm);
    float* w1t    = sm + H_W1_FL;
    float* part   = sm + H_PART_FL;
    float* logits = sm + H_LOG_FL;

    const int tid = threadIdx.x;
    const int lane = tid & 31, wid = tid >> 5;
    const int g = lane >> 2, tig = lane & 3;
    const int warpN = wid;
    const int rowBase = blockIdx.x * 64;

    float acc[64];
#pragma unroll
    for (int i = 0; i < 64; i++) acc[i] = 0.f;

    auto issue = [&](int ch) {
        const uint32_t sBase = smb + (ch & 1) * H_STAGE_B;
        const int kb = ch * 32;
        {
            int r = tid >> 2, q = tid & 3;
            uint32_t so = (uint32_t)r * 64 + (uint32_t)((q ^ ((r >> 1) & 3)) << 4);
            size_t go = (size_t)(rowBase + r) * F + kb + q * 8;
            cpasync16(sBase + so, &g_x4h[go]);
            cpasync16(sBase + 4096 + so, &g_x4l[go]);
        }
#pragma unroll
        for (int l = 0; l < 4; l++) {
            int idx = l * 256 + tid;
            int n = idx >> 2, q = idx & 3;
            uint32_t so = (uint32_t)n * 64 + (uint32_t)((q ^ ((n >> 1) & 3)) << 4);
            size_t go = (size_t)n * F + kb + q * 8;
            cpasync16(sBase + 8192 + so, &g_wHiB[go]);
            cpasync16(sBase + 24576 + so, &g_wLoB[go]);
        }
        CP_COMMIT();
    };

    issue(0);

    const int rA = lane & 15;
    const int rW = (lane & 7) + ((lane >> 4) << 3);
    const int gAsel = lane >> 4;
    const int gWsel = (lane >> 3) & 1;

    for (int ch = 0; ch < 16; ch++) {
        CP_WAIT(0);
        __syncthreads();
        if (ch < 15) issue(ch + 1);

        const uint32_t sBase = smb + (ch & 1) * H_STAGE_B;
#pragma unroll
        for (int s = 0; s < 2; s++) {
            const int granA = 2 * s + gAsel;
            const int granW = 2 * s + gWsel;
            uint32_t ah[4][4], al[4][4];
#pragma unroll
            for (int mt = 0; mt < 4; mt++) {
                int row = mt * 16 + rA;
                uint32_t off = (uint32_t)row * 64
                             + (uint32_t)((granA ^ ((row >> 1) & 3)) << 4);
                ldsm_x4(ah[mt], sBase + off);
                ldsm_x4(al[mt], sBase + 4096 + off);
            }
#pragma unroll
            for (int gi = 0; gi < 2; gi++) {
                int nrow = warpN * 32 + gi * 16 + rW;
                uint32_t off = (uint32_t)nrow * 64
                             + (uint32_t)((granW ^ ((nrow >> 1) & 3)) << 4);
                uint32_t bh[4], bl[4];
                ldsm_x4(bh, sBase + 8192 + off);
                ldsm_x4(bl, sBase + 24576 + off);
#pragma unroll
                for (int j = 0; j < 2; j++) {
                    const int nt = 2 * gi + j;
#pragma unroll
                    for (int mt = 0; mt < 4; mt++) {
                        float* c = &acc[(mt * 4 + nt) * 4];
                        mma_bf16(c, al[mt], &bh[2 * j]);
                        mma_bf16(c, ah[mt], &bl[2 * j]);
                        mma_bf16(c, ah[mt], &bh[2 * j]);
                    }
                }
            }
        }
    }
    __syncthreads();   // all mma reads done before stage smem is reused below

    // ---- epilogue (stage memory reused for w1t/part/logits) ----
    for (int i = tid; i < HID * NCLS; i += 256) {
        int jj = i / NCLS, c = i % NCLS;
        w1t[c * 260 + jj] = w1[i];
    }
#pragma unroll
    for (int i = 0; i < 64; i++) acc[i] = fmaxf(acc[i], 0.f);
    __syncthreads();

#pragma unroll
    for (int c = 0; c < NCLS; c++) {
        float w1v[8];
#pragma unroll
        for (int nt = 0; nt < 4; nt++) {
            int col = warpN * 32 + nt * 8 + 2 * tig;
            w1v[nt * 2]     = w1t[c * 260 + col];
            w1v[nt * 2 + 1] = w1t[c * 260 + col + 1];
        }
#pragma unroll
        for (int mt = 0; mt < 4; mt++)
#pragma unroll
            for (int rr = 0; rr < 2; rr++) {
                float s = 0.f;
#pragma unroll
                for (int nt = 0; nt < 4; nt++) {
                    s += acc[(mt * 4 + nt) * 4 + rr * 2]     * w1v[nt * 2];
                    s += acc[(mt * 4 + nt) * 4 + rr * 2 + 1] * w1v[nt * 2 + 1];
                }
                s += __shfl_xor_sync(0xffffffffu, s, 1);
                s += __shfl_xor_sync(0xffffffffu, s, 2);
                if (tig == 0) {
                    int row = mt * 16 + g + rr * 8;
                    part[warpN * (64 * NCLS) + row * NCLS + c] = s;
                }
            }
    }
    __syncthreads();

    for (int i = tid; i < 64 * NCLS; i += 256) {
        float t = 0.f;
#pragma unroll
        for (int wz = 0; wz < 8; wz++) t += part[wz * (64 * NCLS) + i];
        logits[i] = t;
    }
    __syncthreads();

    if (tid < 64) {
        int row = rowBase + tid;
        int yr = y[row];
        const float* lg = &logits[tid * NCLS];
        float m = lg[0]; int bi = 0;
#pragma unroll
        for (int c = 1; c < NCLS; c++) if (lg[c] > m) { m = lg[c]; bi = c; }
        float se = 0.f;
#pragma unroll
        for (int c = 0; c < NCLS; c++) se += __expf(lg[c] - m);
        float ce_loc = (m + __logf(se)) - lg[yr];
        float corr_loc = (bi == yr) ? 1.f : 0.f;
#pragma unroll
        for (int o = 16; o; o >>= 1) {
            ce_loc += __shfl_xor_sync(0xffffffffu, ce_loc, o);
            corr_loc += __shfl_xor_sync(0xffffffffu, corr_loc, o);
        }
        if ((tid & 31) == 0) {
            atomicAdd(&g_ce, (double)ce_loc);
            atomicAdd(&g_acc, (double)corr_loc);
        }
    }

    // ---- fused finalization: release-increment done counter; winner CTA
    // acquires once and assembles the final loss/acc. All cross-CTA data
    // (g_ce, g_acc) are atomics; everything else is from prior kernels.
    __shared__ int amLast;
    if (tid == 0) {
        int old;
        asm volatile("atom.release.gpu.global.add.s32 %0, [%1], %2;"
                     : "=r"(old) : "l"(&g_done), "r"(1) : "memory");
        amLast = (old == (int)gridDim.x - 1);
    }
    __syncthreads();
    if (amLast) {
        asm volatile("fence.acq_rel.gpu;" ::: "memory");  // one IVALL, winner only
        float t = 0.f;
        for (int i = tid; i < NCLS * F; i += 256) {
            int c = i / F;
            int cnt = g_counts[c]; if (cnt < 1) cnt = 1;
            float v = g_fsum[i];
            t += v * v / (float)cnt;
        }
#pragma unroll
        for (int o = 16; o; o >>= 1) t += __shfl_xor_sync(0xffffffffu, t, o);
        float* red = logits;  // reuse smem (safe: winner past all logits reads)
        if ((tid & 31) == 0) red[tid >> 5] = t;
        __syncthreads();
        if (tid == 0) {
            double tt = 0.0;
            for (int i = 0; i < 8; i++) tt += (double)red[i];
            double l1 = 0.0;
            for (int i = 0; i < 32; i++) l1 += (double)g_l1part[i];
            double var = g_s2 - tt;
            double loss = g_ce / (double)BATCH + 1e-4 * l1 + 1e-3 * var;
            out[0] = (float)loss;
            out[1] = (float)(g_acc / (double)BATCH);
        }
    }
}

// ---------------- launch ----------------
extern "C" void kernel_launch(void* const* d_in, const int* in_sizes, int n_in,
                              void* d_out, int out_size) {
    const float* x   = (const float*)d_in[0];
    const int*   y   = (const int*)d_in[1];
    const float* fc0 = (const float*)d_in[2];
    const float* fc1 = (const float*)d_in[3];
    const float* w   = (const float*)d_in[4];
    const float* w1  = (const float*)d_in[5];
    float* out = (float*)d_out;

    static int configured = 0;
    if (!configured) {
        cudaFuncSetAttribute(gate_kernel, cudaFuncAttributeMaxDynamicSharedMemorySize,
                             GATE_FL * 4);
        cudaFuncSetAttribute(head_kernel, cudaFuncAttributeMaxDynamicSharedMemorySize,
                             HEAD_FL * 4);
        configured = 1;
    }

    prep_kernel<<<418, 1024>>>(fc0, fc1, w, w1, y);
    gate_kernel<<<dim3(F / 64, BATCH / 128), 256, GATE_FL * 4>>>(x, y);
    head_kernel<<<BATCH / 64, 256, HEAD_FL * 4>>>(w1, y, out);
}

// round 13
// speedup vs baseline: 1.0911x; 1.0911x over previous
#include <cuda_runtime.h>
#include <cuda_bf16.h>
#include <math.h>
#include <stdint.h>

#define BATCH 65536
#define F     512
#define HID   256
#define NCLS  10

// ---------------- scratch ----------------
__device__ __align__(16) unsigned short g_x4h[(size_t)BATCH * F];  // 64 MB
__device__ __align__(16) unsigned short g_x4l[(size_t)BATCH * F];  // 64 MB
__device__ float  g_fc0T[F * F];
__device__ float  g_fc1T[F * F];
__device__ __align__(16) unsigned short g_wHiB[HID * F];
__device__ __align__(16) unsigned short g_wLoB[HID * F];
__device__ float  g_fsum[NCLS * F];
__device__ float  g_l1part[32];
__device__ int    g_histpart[32 * NCLS];
__device__ double g_s2, g_ce, g_acc;

// ---------------- helpers ----------------
__device__ __forceinline__ uint32_t smem_u32(const void* p) {
    uint32_t a;
    asm("{ .reg .u64 t; cvta.to.shared.u64 t, %1; cvt.u32.u64 %0, t; }"
        : "=r"(a) : "l"(p));
    return a;
}
__device__ __forceinline__ void cpasync16(uint32_t dst, const void* src) {
    asm volatile("cp.async.cg.shared.global [%0], [%1], 16;"
                 :: "r"(dst), "l"(src) : "memory");
}
#define CP_COMMIT() asm volatile("cp.async.commit_group;" ::: "memory")
#define CP_WAIT(n)  asm volatile("cp.async.wait_group %0;" :: "n"(n) : "memory")

__device__ __forceinline__ void ldsm_x4(uint32_t* r, uint32_t addr) {
    asm volatile("ldmatrix.sync.aligned.m8n8.x4.shared.b16 {%0,%1,%2,%3}, [%4];"
                 : "=r"(r[0]), "=r"(r[1]), "=r"(r[2]), "=r"(r[3]) : "r"(addr));
}
__device__ __forceinline__ void mma_tf32(float* c, const uint32_t* a, const uint32_t* b) {
    asm volatile("mma.sync.aligned.m16n8k8.row.col.f32.tf32.tf32.f32 "
                 "{%0,%1,%2,%3}, {%4,%5,%6,%7}, {%8,%9}, {%0,%1,%2,%3};"
                 : "+f"(c[0]), "+f"(c[1]), "+f"(c[2]), "+f"(c[3])
                 : "r"(a[0]), "r"(a[1]), "r"(a[2]), "r"(a[3]), "r"(b[0]), "r"(b[1]));
}
__device__ __forceinline__ void mma_bf16(float* c, const uint32_t* a, const uint32_t* b) {
    asm volatile("mma.sync.aligned.m16n8k16.row.col.f32.bf16.bf16.f32 "
                 "{%0,%1,%2,%3}, {%4,%5,%6,%7}, {%8,%9}, {%0,%1,%2,%3};"
                 : "+f"(c[0]), "+f"(c[1]), "+f"(c[2]), "+f"(c[3])
                 : "r"(a[0]), "r"(a[1]), "r"(a[2]), "r"(a[3]), "r"(b[0]), "r"(b[1]));
}

// ================= prep: transposes + l1 partials + hist partials + init =================
// blocks 0-255: fc0/fc1 transpose; 256-383: w bf16 hi/lo split;
// 384-415: l1 partials; 416-447: histogram partials (2048 elems each);
// 448: zero fsum + scalar accumulators.
__global__ __launch_bounds__(1024) void prep_kernel(
    const float* __restrict__ fc0, const float* __restrict__ fc1,
    const float* __restrict__ w, const float* __restrict__ w1,
    const int* __restrict__ y)
{
    __shared__ float t0[32][33];
    __shared__ float t1[32][33];
    __shared__ int   hh[NCLS];
    __shared__ float red[32];
    const int b = blockIdx.x;
    const int tid = threadIdx.x;

    if (b < 256) {
        int bx = (b & 15) * 32, by = (b >> 4) * 32;
        int txi = tid & 31, tyi = tid >> 5;
        t0[tyi][txi] = fc0[(by + tyi) * F + bx + txi];
        t1[tyi][txi] = fc1[(by + tyi) * F + bx + txi];
        __syncthreads();
        g_fc0T[(bx + tyi) * F + by + txi] = t0[txi][tyi];
        g_fc1T[(bx + tyi) * F + by + txi] = t1[txi][tyi];
    } else if (b < 384) {
        int bb = b - 256;
        int bx = (bb & 7) * 32, by = (bb >> 3) * 32;
        int txi = tid & 31, tyi = tid >> 5;
        t0[tyi][txi] = w[(by + tyi) * HID + bx + txi];
        __syncthreads();
        float v = t0[txi][tyi];
        __nv_bfloat16 hb = __float2bfloat16(v);
        float hf = __bfloat162float(hb);
        __nv_bfloat16 lb = __float2bfloat16(v - hf);
        size_t o = (size_t)(bx + tyi) * F + by + txi;
        g_wHiB[o] = *(unsigned short*)&hb;
        g_wLoB[o] = *(unsigned short*)&lb;
    } else if (b < 416) {
        float s = 0.f;
        int i0 = (b - 384) * 1024 + tid;
        const int stride = 32 * 1024;
        for (int k = i0; k < F * F; k += stride) s += fabsf(fc0[k]) + fabsf(fc1[k]);
        for (int k = i0; k < F * HID; k += stride) s += fabsf(w[k]);
        for (int k = i0; k < HID * NCLS; k += stride) s += fabsf(w1[k]);
#pragma unroll
        for (int o = 16; o; o >>= 1) s += __shfl_xor_sync(0xffffffffu, s, o);
        if ((tid & 31) == 0) red[tid >> 5] = s;
        __syncthreads();
        if (tid == 0) {
            float t = 0.f;
            for (int i = 0; i < 32; i++) t += red[i];
            g_l1part[b - 384] = t;
        }
    } else if (b < 448) {
        const int p = b - 416;
        if (tid < NCLS) hh[tid] = 0;
        __syncthreads();
        int base = p * 2048;
        atomicAdd(&hh[y[base + tid]], 1);
        atomicAdd(&hh[y[base + 1024 + tid]], 1);
        __syncthreads();
        if (tid < NCLS) g_histpart[p * NCLS + tid] = hh[tid];
    } else {
        for (int i = tid; i < NCLS * F; i += 1024) g_fsum[i] = 0.f;
        if (tid == 0) { g_s2 = 0.0; g_ce = 0.0; g_acc = 0.0; }
    }
}

// ============ gate: x4 = x + (1+sigmoid(x@fc0))*relu(x@fc1) ============
// CTA 128 rows x 64 logical cols, 256 threads, 2 CTAs/SM.
// Single-sync pipeline: WAIT(1) -> sync -> mma(ch) -> issue(ch+2).
#define G_STAGE_FL 8192
#define G_CSUM_FL  (3 * G_STAGE_FL)
#define G_RED_FL   (G_CSUM_FL + NCLS * 68)
#define GATE_FL    (G_RED_FL + 8)

__global__ __launch_bounds__(256, 2) void gate_kernel(
    const float* __restrict__ x, const int* __restrict__ y)
{
    extern __shared__ float sm[];
    const uint32_t smb = smem_u32(sm);
    float* csum = sm + G_CSUM_FL;
    float* red  = sm + G_RED_FL;

    const int tid = threadIdx.x;
    const int lane = tid & 31, wid = tid >> 5;
    const int g = lane >> 2, tig = lane & 3;
    const int lane7 = lane & 7;
    const int warpM = wid & 3, warpN = wid >> 2;
    const int rowBase = blockIdx.y * 128;
    const int colBase = blockIdx.x * 64;

    const int rowoffA = ((lane >> 3) & 1) * 8 + lane7;
    const int hA = lane >> 4;
    const int rowoffB = ((lane >> 4) & 1) * 8 + lane7;
    const int hB = (lane >> 3) & 1;

    for (int i = tid; i < NCLS * 68; i += 256) csum[i] = 0.f;

    float acc[2][8][4];
#pragma unroll
    for (int mt = 0; mt < 2; mt++)
#pragma unroll
        for (int nt = 0; nt < 8; nt++)
#pragma unroll
            for (int r = 0; r < 4; r++) acc[mt][nt][r] = 0.f;

    auto issue = [&](int ch) {
        const int p = ch % 3;
        const uint32_t sA = smb + p * (G_STAGE_FL * 4);
        const uint32_t sB = sA + 16384;
        const int kb = ch * 32;
#pragma unroll
        for (int l = 0; l < 4; l++) {
            int idx = l * 256 + tid;
            int r = idx >> 3, q = idx & 7;
            cpasync16(sA + (r * 8 + (q ^ (r & 7))) * 16,
                      &x[(size_t)(rowBase + r) * F + kb + q * 4]);
        }
#pragma unroll
        for (int l = 0; l < 4; l++) {
            int idx = l * 256 + tid;
            int nb = idx >> 3, q = idx & 7;
            int m = (nb >> 3) & 1;
            int L = ((nb >> 4) << 3) | (nb & 7);
            const float* src = (m ? g_fc1T : g_fc0T)
                             + (size_t)(colBase + L) * F + kb + q * 4;
            cpasync16(sB + (nb * 8 + (q ^ (nb & 7))) * 16, src);
        }
        CP_COMMIT();
    };

    issue(0);
    issue(1);

    for (int ch = 0; ch < 16; ch++) {
        CP_WAIT(1);
        __syncthreads();

        const uint32_t stBase = smb + (ch % 3) * (G_STAGE_FL * 4);
        const uint32_t aB0 = stBase + (uint32_t)(warpM * 32 + rowoffA) * 128;
        const uint32_t bB  = stBase + 16384;
        uint32_t bAddr[4];
#pragma unroll
        for (int gi = 0; gi < 4; gi++)
            bAddr[gi] = bB + (uint32_t)(warpN * 64 + gi * 16 + rowoffB) * 128;

#pragma unroll
        for (int s = 0; s < 4; s++) {
            const uint32_t offA = (uint32_t)(((2 * s + hA) ^ lane7) << 4);
            const uint32_t offB = (uint32_t)(((2 * s + hB) ^ lane7) << 4);
            uint32_t a[2][4];
            ldsm_x4(a[0], aB0 + offA);
            ldsm_x4(a[1], aB0 + 2048 + offA);
            uint32_t bq[4][4];
#pragma unroll
            for (int gi = 0; gi < 4; gi++) ldsm_x4(bq[gi], bAddr[gi] + offB);
#pragma unroll
            for (int mt = 0; mt < 2; mt++)
#pragma unroll
                for (int gi = 0; gi < 4; gi++) {
                    mma_tf32(acc[mt][2 * gi],     a[mt], &bq[gi][0]);
                    mma_tf32(acc[mt][2 * gi + 1], a[mt], &bq[gi][2]);
                }
        }

        if (ch < 14) issue(ch + 2); else CP_COMMIT();
    }

    // ---- epilogue: x4 -> bf16 hi/lo split, s2, class sums ----
    float s2loc = 0.f;
#pragma unroll
    for (int mt = 0; mt < 2; mt++) {
        int r0 = rowBase + warpM * 32 + mt * 16 + g;
        int r1 = r0 + 8;
        int y0 = y[r0], y1 = y[r1];
#pragma unroll
        for (int j = 0; j < 4; j++) {
            int lcol = warpN * 32 + j * 8 + 2 * tig;
            int gcol = colBase + lcol;
#pragma unroll
            for (int rr = 0; rr < 2; rr++) {
                int row = rr ? r1 : r0;
                int yr = rr ? y1 : y0;
                float A0x = acc[mt][2 * j][rr * 2],     A0y = acc[mt][2 * j][rr * 2 + 1];
                float A1x = acc[mt][2 * j + 1][rr * 2], A1y = acc[mt][2 * j + 1][rr * 2 + 1];
                float2 xv = *(const float2*)&x[(size_t)row * F + gcol];
                float gx = 1.f + __fdividef(1.f, 1.f + __expf(-A0x));
                float gy = 1.f + __fdividef(1.f, 1.f + __expf(-A0y));
                float ox = xv.x + gx * fmaxf(A1x, 0.f);
                float oy = xv.y + gy * fmaxf(A1y, 0.f);
                __nv_bfloat162 hv = __floats2bfloat162_rn(ox, oy);
                *(uint32_t*)&g_x4h[(size_t)row * F + gcol] = *(uint32_t*)&hv;
                float lx = ox - __bfloat162float(hv.x);
                float ly = oy - __bfloat162float(hv.y);
                __nv_bfloat162 lv = __floats2bfloat162_rn(lx, ly);
                *(uint32_t*)&g_x4l[(size_t)row * F + gcol] = *(uint32_t*)&lv;
                s2loc += ox * ox + oy * oy;
                atomicAdd(&csum[yr * 68 + lcol], ox);
                atomicAdd(&csum[yr * 68 + lcol + 1], oy);
            }
        }
    }
    __syncthreads();

    for (int i = tid; i < NCLS * 64; i += 256) {
        int c = i >> 6, col = i & 63;
        float v = csum[c * 68 + col];
        if (v != 0.f) atomicAdd(&g_fsum[c * F + colBase + col], v);
    }
#pragma unroll
    for (int o = 16; o; o >>= 1) s2loc += __shfl_xor_sync(0xffffffffu, s2loc, o);
    if (lane == 0) red[wid] = s2loc;
    __syncthreads();
    if (tid == 0) {
        float t = 0.f;
        for (int i = 0; i < 8; i++) t += red[i];
        atomicAdd(&g_s2, (double)t);
    }
}

// ============ head: relu(x4@w)@w1, 3-term bf16, BM=64, 2 CTAs/SM ============
// Single-sync pipeline: WAIT(0) -> sync -> issue(ch+1) -> mma(ch).
#define H_STAGE_B  40960
#define H_U_FL     20480
#define H_W1_FL    (H_U_FL)
#define H_PART_FL  (H_U_FL + 2600)
#define H_LOG_FL   (H_PART_FL + 5120)
#define HEAD_FL    (H_LOG_FL + 640)

__global__ __launch_bounds__(256, 2) void head_kernel(
    const float* __restrict__ w1, const int* __restrict__ y)
{
    extern __shared__ float sm[];
    const uint32_t smb = smem_u32(sm);
    float* w1t    = sm + H_W1_FL;
    float* part   = sm + H_PART_FL;
    float* logits = sm + H_LOG_FL;

    const int tid = threadIdx.x;
    const int lane = tid & 31, wid = tid >> 5;
    const int g = lane >> 2, tig = lane & 3;
    const int warpN = wid;
    const int rowBase = blockIdx.x * 64;

    float acc[64];
#pragma unroll
    for (int i = 0; i < 64; i++) acc[i] = 0.f;

    auto issue = [&](int ch) {
        const uint32_t sBase = smb + (ch & 1) * H_STAGE_B;
        const int kb = ch * 32;
        {
            int r = tid >> 2, q = tid & 3;
            uint32_t so = (uint32_t)r * 64 + (uint32_t)((q ^ ((r >> 1) & 3)) << 4);
            size_t go = (size_t)(rowBase + r) * F + kb + q * 8;
            cpasync16(sBase + so, &g_x4h[go]);
            cpasync16(sBase + 4096 + so, &g_x4l[go]);
        }
#pragma unroll
        for (int l = 0; l < 4; l++) {
            int idx = l * 256 + tid;
            int n = idx >> 2, q = idx & 3;
            uint32_t so = (uint32_t)n * 64 + (uint32_t)((q ^ ((n >> 1) & 3)) << 4);
            size_t go = (size_t)n * F + kb + q * 8;
            cpasync16(sBase + 8192 + so, &g_wHiB[go]);
            cpasync16(sBase + 24576 + so, &g_wLoB[go]);
        }
        CP_COMMIT();
    };

    issue(0);

    const int rA = lane & 15;
    const int rW = (lane & 7) + ((lane >> 4) << 3);
    const int gAsel = lane >> 4;
    const int gWsel = (lane >> 3) & 1;

    for (int ch = 0; ch < 16; ch++) {
        CP_WAIT(0);
        __syncthreads();
        if (ch < 15) issue(ch + 1);

        const uint32_t sBase = smb + (ch & 1) * H_STAGE_B;
#pragma unroll
        for (int s = 0; s < 2; s++) {
            const int granA = 2 * s + gAsel;
            const int granW = 2 * s + gWsel;
            uint32_t ah[4][4], al[4][4];
#pragma unroll
            for (int mt = 0; mt < 4; mt++) {
                int row = mt * 16 + rA;
                uint32_t off = (uint32_t)row * 64
                             + (uint32_t)((granA ^ ((row >> 1) & 3)) << 4);
                ldsm_x4(ah[mt], sBase + off);
                ldsm_x4(al[mt], sBase + 4096 + off);
            }
#pragma unroll
            for (int gi = 0; gi < 2; gi++) {
                int nrow = warpN * 32 + gi * 16 + rW;
                uint32_t off = (uint32_t)nrow * 64
                             + (uint32_t)((granW ^ ((nrow >> 1) & 3)) << 4);
                uint32_t bh[4], bl[4];
                ldsm_x4(bh, sBase + 8192 + off);
                ldsm_x4(bl, sBase + 24576 + off);
#pragma unroll
                for (int j = 0; j < 2; j++) {
                    const int nt = 2 * gi + j;
#pragma unroll
                    for (int mt = 0; mt < 4; mt++) {
                        float* c = &acc[(mt * 4 + nt) * 4];
                        mma_bf16(c, al[mt], &bh[2 * j]);
                        mma_bf16(c, ah[mt], &bl[2 * j]);
                        mma_bf16(c, ah[mt], &bh[2 * j]);
                    }
                }
            }
        }
    }
    __syncthreads();   // all mma reads done before stage smem is reused below

    // ---- epilogue (stage memory reused for w1t/part/logits) ----
    for (int i = tid; i < HID * NCLS; i += 256) {
        int jj = i / NCLS, c = i % NCLS;
        w1t[c * 260 + jj] = w1[i];
    }
#pragma unroll
    for (int i = 0; i < 64; i++) acc[i] = fmaxf(acc[i], 0.f);
    __syncthreads();

#pragma unroll
    for (int c = 0; c < NCLS; c++) {
        float w1v[8];
#pragma unroll
        for (int nt = 0; nt < 4; nt++) {
            int col = warpN * 32 + nt * 8 + 2 * tig;
            w1v[nt * 2]     = w1t[c * 260 + col];
            w1v[nt * 2 + 1] = w1t[c * 260 + col + 1];
        }
#pragma unroll
        for (int mt = 0; mt < 4; mt++)
#pragma unroll
            for (int rr = 0; rr < 2; rr++) {
                float s = 0.f;
#pragma unroll
                for (int nt = 0; nt < 4; nt++) {
                    s += acc[(mt * 4 + nt) * 4 + rr * 2]     * w1v[nt * 2];
                    s += acc[(mt * 4 + nt) * 4 + rr * 2 + 1] * w1v[nt * 2 + 1];
                }
                s += __shfl_xor_sync(0xffffffffu, s, 1);
                s += __shfl_xor_sync(0xffffffffu, s, 2);
                if (tig == 0) {
                    int row = mt * 16 + g + rr * 8;
                    part[warpN * (64 * NCLS) + row * NCLS + c] = s;
                }
            }
    }
    __syncthreads();

    for (int i = tid; i < 64 * NCLS; i += 256) {
        float t = 0.f;
#pragma unroll
        for (int wz = 0; wz < 8; wz++) t += part[wz * (64 * NCLS) + i];
        logits[i] = t;
    }
    __syncthreads();

    if (tid < 64) {
        int row = rowBase + tid;
        int yr = y[row];
        const float* lg = &logits[tid * NCLS];
        float m = lg[0]; int bi = 0;
#pragma unroll
        for (int c = 1; c < NCLS; c++) if (lg[c] > m) { m = lg[c]; bi = c; }
        float se = 0.f;
#pragma unroll
        for (int c = 0; c < NCLS; c++) se += __expf(lg[c] - m);
        float ce_loc = (m + __logf(se)) - lg[yr];
        float corr_loc = (bi == yr) ? 1.f : 0.f;
#pragma unroll
        for (int o = 16; o; o >>= 1) {
            ce_loc += __shfl_xor_sync(0xffffffffu, ce_loc, o);
            corr_loc += __shfl_xor_sync(0xffffffffu, corr_loc, o);
        }
        if ((tid & 31) == 0) {
            atomicAdd(&g_ce, (double)ce_loc);
            atomicAdd(&g_acc, (double)corr_loc);
        }
    }
}

// ---------------- finalize (parallel reductions, no serial thread-0 loops) ----------------
__global__ __launch_bounds__(1024) void final_kernel(float* __restrict__ out) {
    __shared__ int   counts_sm[NCLS];
    __shared__ float red[32];
    __shared__ float l1red;
    const int tid = threadIdx.x;

    if (tid < NCLS) counts_sm[tid] = 0;
    __syncthreads();
    if (tid < 32 * NCLS)
        atomicAdd(&counts_sm[tid % NCLS], g_histpart[(tid / NCLS) * NCLS + tid % NCLS]);
    // l1 reduction in warp 1 (threads 32..63)
    if (tid >= 32 && tid < 64) {
        float s = g_l1part[tid - 32];
#pragma unroll
        for (int o = 16; o; o >>= 1) s += __shfl_xor_sync(0xffffffffu, s, o);
        if (tid == 32) l1red = s;
    }
    __syncthreads();

    float t = 0.f;
    for (int i = tid; i < NCLS * F; i += 1024) {
        int c = i / F;
        int cnt = counts_sm[c]; if (cnt < 1) cnt = 1;
        float v = g_fsum[i];
        t += v * v / (float)cnt;
    }
#pragma unroll
    for (int o = 16; o; o >>= 1) t += __shfl_xor_sync(0xffffffffu, t, o);
    if ((tid & 31) == 0) red[tid >> 5] = t;
    __syncthreads();
    if (tid < 32) {
        float s = red[tid];
#pragma unroll
        for (int o = 16; o; o >>= 1) s += __shfl_xor_sync(0xffffffffu, s, o);
        if (tid == 0) {
            double var = g_s2 - (double)s;
            double loss = g_ce / (double)BATCH + 1e-4 * (double)l1red + 1e-3 * var;
            out[0] = (float)loss;
            out[1] = (float)(g_acc / (double)BATCH);
        }
    }
}

// ---------------- launch ----------------
extern "C" void kernel_launch(void* const* d_in, const int* in_sizes, int n_in,
                              void* d_out, int out_size) {
    const float* x   = (const float*)d_in[0];
    const int*   y   = (const int*)d_in[1];
    const float* fc0 = (const float*)d_in[2];
    const float* fc1 = (const float*)d_in[3];
    const float* w   = (const float*)d_in[4];
    const float* w1  = (const float*)d_in[5];
    float* out = (float*)d_out;

    static int configured = 0;
    if (!configured) {
        cudaFuncSetAttribute(gate_kernel, cudaFuncAttributeMaxDynamicSharedMemorySize,
                             GATE_FL * 4);
        cudaFuncSetAttribute(head_kernel, cudaFuncAttributeMaxDynamicSharedMemorySize,
                             HEAD_FL * 4);
        configured = 1;
    }

    prep_kernel<<<449, 1024>>>(fc0, fc1, w, w1, y);
    gate_kernel<<<dim3(F / 64, BATCH / 128), 256, GATE_FL * 4>>>(x, y);
    head_kernel<<<BATCH / 64, 256, HEAD_FL * 4>>>(w1, y);
    final_kernel<<<1, 1024>>>(out);
}

// round 14
// speedup vs baseline: 1.0960x; 1.0044x over previous
#include <cuda_runtime.h>
#include <cuda_bf16.h>
#include <math.h>
#include <stdint.h>

#define BATCH 65536
#define F     512
#define HID   256
#define NCLS  10

// ---------------- scratch ----------------
__device__ __align__(16) unsigned short g_x4h[(size_t)BATCH * F];  // 64 MB
__device__ __align__(16) unsigned short g_x4l[(size_t)BATCH * F];  // 64 MB
__device__ float  g_fc0T[F * F];
__device__ float  g_fc1T[F * F];
__device__ __align__(16) unsigned short g_wHiB[HID * F];
__device__ __align__(16) unsigned short g_wLoB[HID * F];
__device__ __align__(16) float g_fsum[NCLS * F];
__device__ float  g_l1part[32];
__device__ int    g_histpart[32 * NCLS];
__device__ double g_s2, g_ce, g_acc;

// ---------------- helpers ----------------
__device__ __forceinline__ uint32_t smem_u32(const void* p) {
    uint32_t a;
    asm("{ .reg .u64 t; cvta.to.shared.u64 t, %1; cvt.u32.u64 %0, t; }"
        : "=r"(a) : "l"(p));
    return a;
}
__device__ __forceinline__ void cpasync16(uint32_t dst, const void* src) {
    asm volatile("cp.async.cg.shared.global [%0], [%1], 16;"
                 :: "r"(dst), "l"(src) : "memory");
}
#define CP_COMMIT() asm volatile("cp.async.commit_group;" ::: "memory")
#define CP_WAIT(n)  asm volatile("cp.async.wait_group %0;" :: "n"(n) : "memory")

__device__ __forceinline__ void ldsm_x4(uint32_t* r, uint32_t addr) {
    asm volatile("ldmatrix.sync.aligned.m8n8.x4.shared.b16 {%0,%1,%2,%3}, [%4];"
                 : "=r"(r[0]), "=r"(r[1]), "=r"(r[2]), "=r"(r[3]) : "r"(addr));
}
__device__ __forceinline__ void mma_tf32(float* c, const uint32_t* a, const uint32_t* b) {
    asm volatile("mma.sync.aligned.m16n8k8.row.col.f32.tf32.tf32.f32 "
                 "{%0,%1,%2,%3}, {%4,%5,%6,%7}, {%8,%9}, {%0,%1,%2,%3};"
                 : "+f"(c[0]), "+f"(c[1]), "+f"(c[2]), "+f"(c[3])
                 : "r"(a[0]), "r"(a[1]), "r"(a[2]), "r"(a[3]), "r"(b[0]), "r"(b[1]));
}
__device__ __forceinline__ void mma_bf16(float* c, const uint32_t* a, const uint32_t* b) {
    asm volatile("mma.sync.aligned.m16n8k16.row.col.f32.bf16.bf16.f32 "
                 "{%0,%1,%2,%3}, {%4,%5,%6,%7}, {%8,%9}, {%0,%1,%2,%3};"
                 : "+f"(c[0]), "+f"(c[1]), "+f"(c[2]), "+f"(c[3])
                 : "r"(a[0]), "r"(a[1]), "r"(a[2]), "r"(a[3]), "r"(b[0]), "r"(b[1]));
}

// ================= prep: 64x64 transposes + l1 partials + hist partials + init =================
// blocks 0-63: fc0/fc1 transpose; 64-95: w bf16 hi/lo transpose;
// 96-127: l1 partials; 128-159: histogram partials; 160: zero fsum + init.
__global__ __launch_bounds__(1024) void prep_kernel(
    const float* __restrict__ fc0, const float* __restrict__ fc1,
    const float* __restrict__ w, const float* __restrict__ w1,
    const int* __restrict__ y)
{
    __shared__ float t0[64][65];
    __shared__ float t1[64][65];
    __shared__ int   hh[NCLS];
    __shared__ float red[32];
    const int b = blockIdx.x;
    const int tid = threadIdx.x;
    const int txi = tid & 31, tyi = tid >> 5;

    if (b < 64) {
        int bx = (b & 7) * 64, by = (b >> 3) * 64;
#pragma unroll
        for (int dy = 0; dy < 64; dy += 32)
#pragma unroll
            for (int dx = 0; dx < 64; dx += 32) {
                t0[tyi + dy][txi + dx] = fc0[(by + tyi + dy) * F + bx + txi + dx];
                t1[tyi + dy][txi + dx] = fc1[(by + tyi + dy) * F + bx + txi + dx];
            }
        __syncthreads();
#pragma unroll
        for (int dy = 0; dy < 64; dy += 32)
#pragma unroll
            for (int dx = 0; dx < 64; dx += 32) {
                g_fc0T[(bx + tyi + dy) * F + by + txi + dx] = t0[txi + dx][tyi + dy];
                g_fc1T[(bx + tyi + dy) * F + by + txi + dx] = t1[txi + dx][tyi + dy];
            }
    } else if (b < 96) {
        int bb = b - 64;
        int bx = (bb & 3) * 64, by = (bb >> 2) * 64;   // bx over HID, by over F
#pragma unroll
        for (int dy = 0; dy < 64; dy += 32)
#pragma unroll
            for (int dx = 0; dx < 64; dx += 32)
                t0[tyi + dy][txi + dx] = w[(by + tyi + dy) * HID + bx + txi + dx];
        __syncthreads();
#pragma unroll
        for (int dy = 0; dy < 64; dy += 32)
#pragma unroll
            for (int dx = 0; dx < 64; dx += 32) {
                float v = t0[txi + dx][tyi + dy];
                __nv_bfloat16 hb = __float2bfloat16(v);
                float hf = __bfloat162float(hb);
                __nv_bfloat16 lb = __float2bfloat16(v - hf);
                size_t o = (size_t)(bx + tyi + dy) * F + by + txi + dx;
                g_wHiB[o] = *(unsigned short*)&hb;
                g_wLoB[o] = *(unsigned short*)&lb;
            }
    } else if (b < 128) {
        float s = 0.f;
        int i0 = (b - 96) * 1024 + tid;
        const int stride = 32 * 1024;
        for (int k = i0; k < F * F; k += stride) s += fabsf(fc0[k]) + fabsf(fc1[k]);
        for (int k = i0; k < F * HID; k += stride) s += fabsf(w[k]);
        for (int k = i0; k < HID * NCLS; k += stride) s += fabsf(w1[k]);
#pragma unroll
        for (int o = 16; o; o >>= 1) s += __shfl_xor_sync(0xffffffffu, s, o);
        if ((tid & 31) == 0) red[tid >> 5] = s;
        __syncthreads();
        if (tid == 0) {
            float t = 0.f;
            for (int i = 0; i < 32; i++) t += red[i];
            g_l1part[b - 96] = t;
        }
    } else if (b < 160) {
        const int p = b - 128;
        if (tid < NCLS) hh[tid] = 0;
        __syncthreads();
        int base = p * 2048;
        atomicAdd(&hh[y[base + tid]], 1);
        atomicAdd(&hh[y[base + 1024 + tid]], 1);
        __syncthreads();
        if (tid < NCLS) g_histpart[p * NCLS + tid] = hh[tid];
    } else {
        for (int i = tid; i < NCLS * F; i += 1024) g_fsum[i] = 0.f;
        if (tid == 0) { g_s2 = 0.0; g_ce = 0.0; g_acc = 0.0; }
    }
}

// ============ gate: x4 = x + (1+sigmoid(x@fc0))*relu(x@fc1) ============
// CTA 128 rows x 64 logical cols, 256 threads, 2 CTAs/SM.
// Single-sync pipeline: WAIT(1) -> sync -> mma(ch) -> issue(ch+2).
#define G_STAGE_FL 8192
#define G_CSUM_FL  (3 * G_STAGE_FL)
#define G_RED_FL   (G_CSUM_FL + NCLS * 68)
#define GATE_FL    (G_RED_FL + 8)

__global__ __launch_bounds__(256, 2) void gate_kernel(
    const float* __restrict__ x, const int* __restrict__ y)
{
    extern __shared__ float sm[];
    const uint32_t smb = smem_u32(sm);
    float* csum = sm + G_CSUM_FL;
    float* red  = sm + G_RED_FL;

    const int tid = threadIdx.x;
    const int lane = tid & 31, wid = tid >> 5;
    const int g = lane >> 2, tig = lane & 3;
    const int lane7 = lane & 7;
    const int warpM = wid & 3, warpN = wid >> 2;
    const int rowBase = blockIdx.y * 128;
    const int colBase = blockIdx.x * 64;

    const int rowoffA = ((lane >> 3) & 1) * 8 + lane7;
    const int hA = lane >> 4;
    const int rowoffB = ((lane >> 4) & 1) * 8 + lane7;
    const int hB = (lane >> 3) & 1;

    for (int i = tid; i < NCLS * 68; i += 256) csum[i] = 0.f;

    float acc[2][8][4];
#pragma unroll
    for (int mt = 0; mt < 2; mt++)
#pragma unroll
        for (int nt = 0; nt < 8; nt++)
#pragma unroll
            for (int r = 0; r < 4; r++) acc[mt][nt][r] = 0.f;

    auto issue = [&](int ch) {
        const int p = ch % 3;
        const uint32_t sA = smb + p * (G_STAGE_FL * 4);
        const uint32_t sB = sA + 16384;
        const int kb = ch * 32;
#pragma unroll
        for (int l = 0; l < 4; l++) {
            int idx = l * 256 + tid;
            int r = idx >> 3, q = idx & 7;
            cpasync16(sA + (r * 8 + (q ^ (r & 7))) * 16,
                      &x[(size_t)(rowBase + r) * F + kb + q * 4]);
        }
#pragma unroll
        for (int l = 0; l < 4; l++) {
            int idx = l * 256 + tid;
            int nb = idx >> 3, q = idx & 7;
            int m = (nb >> 3) & 1;
            int L = ((nb >> 4) << 3) | (nb & 7);
            const float* src = (m ? g_fc1T : g_fc0T)
                             + (size_t)(colBase + L) * F + kb + q * 4;
            cpasync16(sB + (nb * 8 + (q ^ (nb & 7))) * 16, src);
        }
        CP_COMMIT();
    };

    issue(0);
    issue(1);

    for (int ch = 0; ch < 16; ch++) {
        CP_WAIT(1);
        __syncthreads();

        const uint32_t stBase = smb + (ch % 3) * (G_STAGE_FL * 4);
        const uint32_t aB0 = stBase + (uint32_t)(warpM * 32 + rowoffA) * 128;
        const uint32_t bB  = stBase + 16384;
        uint32_t bAddr[4];
#pragma unroll
        for (int gi = 0; gi < 4; gi++)
            bAddr[gi] = bB + (uint32_t)(warpN * 64 + gi * 16 + rowoffB) * 128;

#pragma unroll
        for (int s = 0; s < 4; s++) {
            const uint32_t offA = (uint32_t)(((2 * s + hA) ^ lane7) << 4);
            const uint32_t offB = (uint32_t)(((2 * s + hB) ^ lane7) << 4);
            uint32_t a[2][4];
            ldsm_x4(a[0], aB0 + offA);
            ldsm_x4(a[1], aB0 + 2048 + offA);
            uint32_t bq[4][4];
#pragma unroll
            for (int gi = 0; gi < 4; gi++) ldsm_x4(bq[gi], bAddr[gi] + offB);
#pragma unroll
            for (int mt = 0; mt < 2; mt++)
#pragma unroll
                for (int gi = 0; gi < 4; gi++) {
                    mma_tf32(acc[mt][2 * gi],     a[mt], &bq[gi][0]);
                    mma_tf32(acc[mt][2 * gi + 1], a[mt], &bq[gi][2]);
                }
        }

        if (ch < 14) issue(ch + 2); else CP_COMMIT();
    }

    // ---- epilogue: x4 -> bf16 hi/lo split, s2, class sums ----
    float s2loc = 0.f;
#pragma unroll
    for (int mt = 0; mt < 2; mt++) {
        int r0 = rowBase + warpM * 32 + mt * 16 + g;
        int r1 = r0 + 8;
        int y0 = y[r0], y1 = y[r1];
#pragma unroll
        for (int j = 0; j < 4; j++) {
            int lcol = warpN * 32 + j * 8 + 2 * tig;
            int gcol = colBase + lcol;
#pragma unroll
            for (int rr = 0; rr < 2; rr++) {
                int row = rr ? r1 : r0;
                int yr = rr ? y1 : y0;
                float A0x = acc[mt][2 * j][rr * 2],     A0y = acc[mt][2 * j][rr * 2 + 1];
                float A1x = acc[mt][2 * j + 1][rr * 2], A1y = acc[mt][2 * j + 1][rr * 2 + 1];
                float2 xv = *(const float2*)&x[(size_t)row * F + gcol];
                float gx = 1.f + __fdividef(1.f, 1.f + __expf(-A0x));
                float gy = 1.f + __fdividef(1.f, 1.f + __expf(-A0y));
                float ox = xv.x + gx * fmaxf(A1x, 0.f);
                float oy = xv.y + gy * fmaxf(A1y, 0.f);
                __nv_bfloat162 hv = __floats2bfloat162_rn(ox, oy);
                *(uint32_t*)&g_x4h[(size_t)row * F + gcol] = *(uint32_t*)&hv;
                float lx = ox - __bfloat162float(hv.x);
                float ly = oy - __bfloat162float(hv.y);
                __nv_bfloat162 lv = __floats2bfloat162_rn(lx, ly);
                *(uint32_t*)&g_x4l[(size_t)row * F + gcol] = *(uint32_t*)&lv;
                s2loc += ox * ox + oy * oy;
                atomicAdd(&csum[yr * 68 + lcol], ox);
                atomicAdd(&csum[yr * 68 + lcol + 1], oy);
            }
        }
    }
    __syncthreads();

    for (int i = tid; i < NCLS * 64; i += 256) {
        int c = i >> 6, col = i & 63;
        float v = csum[c * 68 + col];
        if (v != 0.f) atomicAdd(&g_fsum[c * F + colBase + col], v);
    }
#pragma unroll
    for (int o = 16; o; o >>= 1) s2loc += __shfl_xor_sync(0xffffffffu, s2loc, o);
    if (lane == 0) red[wid] = s2loc;
    __syncthreads();
    if (tid == 0) {
        float t = 0.f;
        for (int i = 0; i < 8; i++) t += red[i];
        atomicAdd(&g_s2, (double)t);
    }
}

// ============ head: relu(x4@w)@w1, 3-term bf16, BM=64, 2 CTAs/SM ============
// Single-sync pipeline: WAIT(0) -> sync -> issue(ch+1) -> mma(ch).
#define H_STAGE_B  40960
#define H_U_FL     20480
#define H_W1_FL    (H_U_FL)
#define H_PART_FL  (H_U_FL + 2600)
#define H_LOG_FL   (H_PART_FL + 5120)
#define HEAD_FL    (H_LOG_FL + 640)

__global__ __launch_bounds__(256, 2) void head_kernel(
    const float* __restrict__ w1, const int* __restrict__ y)
{
    extern __shared__ float sm[];
    const uint32_t smb = smem_u32(sm);
    float* w1t    = sm + H_W1_FL;
    float* part   = sm + H_PART_FL;
    float* logits = sm + H_LOG_FL;

    const int tid = threadIdx.x;
    const int lane = tid & 31, wid = tid >> 5;
    const int g = lane >> 2, tig = lane & 3;
    const int warpN = wid;
    const int rowBase = blockIdx.x * 64;

    float acc[64];
#pragma unroll
    for (int i = 0; i < 64; i++) acc[i] = 0.f;

    auto issue = [&](int ch) {
        const uint32_t sBase = smb + (ch & 1) * H_STAGE_B;
        const int kb = ch * 32;
        {
            int r = tid >> 2, q = tid & 3;
            uint32_t so = (uint32_t)r * 64 + (uint32_t)((q ^ ((r >> 1) & 3)) << 4);
            size_t go = (size_t)(rowBase + r) * F + kb + q * 8;
            cpasync16(sBase + so, &g_x4h[go]);
            cpasync16(sBase + 4096 + so, &g_x4l[go]);
        }
#pragma unroll
        for (int l = 0; l < 4; l++) {
            int idx = l * 256 + tid;
            int n = idx >> 2, q = idx & 3;
            uint32_t so = (uint32_t)n * 64 + (uint32_t)((q ^ ((n >> 1) & 3)) << 4);
            size_t go = (size_t)n * F + kb + q * 8;
            cpasync16(sBase + 8192 + so, &g_wHiB[go]);
            cpasync16(sBase + 24576 + so, &g_wLoB[go]);
        }
        CP_COMMIT();
    };

    issue(0);

    const int rA = lane & 15;
    const int rW = (lane & 7) + ((lane >> 4) << 3);
    const int gAsel = lane >> 4;
    const int gWsel = (lane >> 3) & 1;

    for (int ch = 0; ch < 16; ch++) {
        CP_WAIT(0);
        __syncthreads();
        if (ch < 15) issue(ch + 1);

        const uint32_t sBase = smb + (ch & 1) * H_STAGE_B;
#pragma unroll
        for (int s = 0; s < 2; s++) {
            const int granA = 2 * s + gAsel;
            const int granW = 2 * s + gWsel;
            uint32_t ah[4][4], al[4][4];
#pragma unroll
            for (int mt = 0; mt < 4; mt++) {
                int row = mt * 16 + rA;
                uint32_t off = (uint32_t)row * 64
                             + (uint32_t)((granA ^ ((row >> 1) & 3)) << 4);
                ldsm_x4(ah[mt], sBase + off);
                ldsm_x4(al[mt], sBase + 4096 + off);
            }
#pragma unroll
            for (int gi = 0; gi < 2; gi++) {
                int nrow = warpN * 32 + gi * 16 + rW;
                uint32_t off = (uint32_t)nrow * 64
                             + (uint32_t)((granW ^ ((nrow >> 1) & 3)) << 4);
                uint32_t bh[4], bl[4];
                ldsm_x4(bh, sBase + 8192 + off);
                ldsm_x4(bl, sBase + 24576 + off);
#pragma unroll
                for (int j = 0; j < 2; j++) {
                    const int nt = 2 * gi + j;
#pragma unroll
                    for (int mt = 0; mt < 4; mt++) {
                        float* c = &acc[(mt * 4 + nt) * 4];
                        mma_bf16(c, al[mt], &bh[2 * j]);
                        mma_bf16(c, ah[mt], &bl[2 * j]);
                        mma_bf16(c, ah[mt], &bh[2 * j]);
                    }
                }
            }
        }
    }
    __syncthreads();   // all mma reads done before stage smem is reused below

    // ---- epilogue (stage memory reused for w1t/part/logits) ----
    for (int i = tid; i < HID * NCLS; i += 256) {
        int jj = i / NCLS, c = i % NCLS;
        w1t[c * 260 + jj] = w1[i];
    }
#pragma unroll
    for (int i = 0; i < 64; i++) acc[i] = fmaxf(acc[i], 0.f);
    __syncthreads();

#pragma unroll
    for (int c = 0; c < NCLS; c++) {
        float w1v[8];
#pragma unroll
        for (int nt = 0; nt < 4; nt++) {
            int col = warpN * 32 + nt * 8 + 2 * tig;
            w1v[nt * 2]     = w1t[c * 260 + col];
            w1v[nt * 2 + 1] = w1t[c * 260 + col + 1];
        }
#pragma unroll
        for (int mt = 0; mt < 4; mt++)
#pragma unroll
            for (int rr = 0; rr < 2; rr++) {
                float s = 0.f;
#pragma unroll
                for (int nt = 0; nt < 4; nt++) {
                    s += acc[(mt * 4 + nt) * 4 + rr * 2]     * w1v[nt * 2];
                    s += acc[(mt * 4 + nt) * 4 + rr * 2 + 1] * w1v[nt * 2 + 1];
                }
                s += __shfl_xor_sync(0xffffffffu, s, 1);
                s += __shfl_xor_sync(0xffffffffu, s, 2);
                if (tig == 0) {
                    int row = mt * 16 + g + rr * 8;
                    part[warpN * (64 * NCLS) + row * NCLS + c] = s;
                }
            }
    }
    __syncthreads();

    for (int i = tid; i < 64 * NCLS; i += 256) {
        float t = 0.f;
#pragma unroll
        for (int wz = 0; wz < 8; wz++) t += part[wz * (64 * NCLS) + i];
        logits[i] = t;
    }
    __syncthreads();

    if (tid < 64) {
        int row = rowBase + tid;
        int yr = y[row];
        const float* lg = &logits[tid * NCLS];
        float m = lg[0]; int bi = 0;
#pragma unroll
        for (int c = 1; c < NCLS; c++) if (lg[c] > m) { m = lg[c]; bi = c; }
        float se = 0.f;
#pragma unroll
        for (int c = 0; c < NCLS; c++) se += __expf(lg[c] - m);
        float ce_loc = (m + __logf(se)) - lg[yr];
        float corr_loc = (bi == yr) ? 1.f : 0.f;
#pragma unroll
        for (int o = 16; o; o >>= 1) {
            ce_loc += __shfl_xor_sync(0xffffffffu, ce_loc, o);
            corr_loc += __shfl_xor_sync(0xffffffffu, corr_loc, o);
        }
        if ((tid & 31) == 0) {
            atomicAdd(&g_ce, (double)ce_loc);
            atomicAdd(&g_acc, (double)corr_loc);
        }
    }
}

// ---------------- finalize (parallel reductions, float4 fsum reads) ----------------
__global__ __launch_bounds__(1024) void final_kernel(float* __restrict__ out) {
    __shared__ int   counts_sm[NCLS];
    __shared__ float red[32];
    __shared__ float l1red;
    const int tid = threadIdx.x;

    if (tid < NCLS) counts_sm[tid] = 0;
    __syncthreads();
    if (tid < 32 * NCLS)
        atomicAdd(&counts_sm[tid % NCLS], g_histpart[(tid / NCLS) * NCLS + tid % NCLS]);
    if (tid >= 32 && tid < 64) {
        float s = g_l1part[tid - 32];
#pragma unroll
        for (int o = 16; o; o >>= 1) s += __shfl_xor_sync(0xffffffffu, s, o);
        if (tid == 32) l1red = s;
    }
    __syncthreads();

    float t = 0.f;
    const float4* fs4 = (const float4*)g_fsum;
    for (int i4 = tid; i4 < NCLS * F / 4; i4 += 1024) {
        int c = i4 >> 7;                       // F/4 = 128 vectors per class
        int cnt = counts_sm[c]; if (cnt < 1) cnt = 1;
        float inv = 1.f / (float)cnt;
        float4 v = fs4[i4];
        t += (v.x * v.x + v.y * v.y + v.z * v.z + v.w * v.w) * inv;
    }
#pragma unroll
    for (int o = 16; o; o >>= 1) t += __shfl_xor_sync(0xffffffffu, t, o);
    if ((tid & 31) == 0) red[tid >> 5] = t;
    __syncthreads();
    if (tid < 32) {
        float s = red[tid];
#pragma unroll
        for (int o = 16; o; o >>= 1) s += __shfl_xor_sync(0xffffffffu, s, o);
        if (tid == 0) {
            double var = g_s2 - (double)s;
            double loss = g_ce / (double)BATCH + 1e-4 * (double)l1red + 1e-3 * var;
            out[0] = (float)loss;
            out[1] = (float)(g_acc / (double)BATCH);
        }
    }
}

// ---------------- launch ----------------
extern "C" void kernel_launch(void* const* d_in, const int* in_sizes, int n_in,
                              void* d_out, int out_size) {
    const float* x   = (const float*)d_in[0];
    const int*   y   = (const int*)d_in[1];
    const float* fc0 = (const float*)d_in[2];
    const float* fc1 = (const float*)d_in[3];
    const float* w   = (const float*)d_in[4];
    const float* w1  = (const float*)d_in[5];
    float* out = (float*)d_out;

    static int configured = 0;
    if (!configured) {
        cudaFuncSetAttribute(gate_kernel, cudaFuncAttributeMaxDynamicSharedMemorySize,
                             GATE_FL * 4);
        cudaFuncSetAttribute(head_kernel, cudaFuncAttributeMaxDynamicSharedMemorySize,
                             HEAD_FL * 4);
        configured = 1;
    }

    prep_kernel<<<161, 1024>>>(fc0, fc1, w, w1, y);
    gate_kernel<<<dim3(F / 64, BATCH / 128), 256, GATE_FL * 4>>>(x, y);
    head_kernel<<<BATCH / 64, 256, HEAD_FL * 4>>>(w1, y);
    final_kernel<<<1, 1024>>>(out);
}